// round 7
// baseline (speedup 1.0000x reference)
#include <cuda_runtime.h>
#include <cuda_bf16.h>

#define BB 2
#define SS 2048
#define DIM 1024
#define HH 16
#define HD 64
#define BSD (BB*SS*DIM)
#define DD  (DIM*DIM)

// ---------------- scratch ----------------
__device__ unsigned g_absmax[8];
__device__ float g_scales[8];
__device__ __align__(256) __nv_bfloat16 g_Xq[BSD];
__device__ __align__(256) __nv_bfloat16 g_Aq[BSD];
__device__ __align__(256) __nv_bfloat16 g_Wb[4][DD];
__device__ __align__(256) float g_Q[BSD];
__device__ __align__(256) float g_Khl[2*BSD];   // hi/lo interleaved along d
__device__ __align__(256) float g_Vhl[2*BSD];
__device__ __align__(256) float g_attn[BSD];

// ---------------- helpers ----------------
__device__ __forceinline__ unsigned f2t(float x) {
    unsigned r;
    asm("cvt.rna.tf32.f32 %0, %1;" : "=r"(r) : "f"(x));
    return r;
}
__device__ __forceinline__ void cpasync16(unsigned saddr, const void* g) {
    asm volatile("cp.async.cg.shared.global [%0], [%1], 16;" :: "r"(saddr), "l"(g));
}
#define CP_COMMIT asm volatile("cp.async.commit_group;")
#define CP_WAIT(n) asm volatile("cp.async.wait_group %0;" :: "n"(n))

__device__ __forceinline__ void ldmat4(unsigned* r, unsigned addr) {
    asm volatile("ldmatrix.sync.aligned.m8n8.x4.shared.b16 {%0,%1,%2,%3},[%4];"
        : "=r"(r[0]), "=r"(r[1]), "=r"(r[2]), "=r"(r[3]) : "r"(addr));
}
__device__ __forceinline__ void mma16816(float* c, const unsigned* a, const unsigned* b) {
    asm volatile("mma.sync.aligned.m16n8k16.row.col.f32.bf16.bf16.f32 "
        "{%0,%1,%2,%3},{%4,%5,%6,%7},{%8,%9},{%0,%1,%2,%3};"
        : "+f"(c[0]), "+f"(c[1]), "+f"(c[2]), "+f"(c[3])
        : "r"(a[0]), "r"(a[1]), "r"(a[2]), "r"(a[3]), "r"(b[0]), "r"(b[1]));
}
#define MMA8(c, a, b0, b1) \
  asm volatile("mma.sync.aligned.m16n8k8.row.col.f32.tf32.tf32.f32 " \
    "{%0,%1,%2,%3},{%4,%5,%6,%7},{%8,%9},{%0,%1,%2,%3};" \
    : "+f"(c[0]), "+f"(c[1]), "+f"(c[2]), "+f"(c[3]) \
    : "r"(a[0]), "r"(a[1]), "r"(a[2]), "r"(a[3]), "r"(b0), "r"(b1))

// ---------------- batched absmax: grid.y = 0 hidden, 1..4 weights ----------------
__global__ void absmax_all_k(const float* __restrict__ h,
                             const float* w0, const float* w1,
                             const float* w2, const float* w3) {
    int y = blockIdx.y;
    const float* x = y == 0 ? h : y == 1 ? w0 : y == 2 ? w1 : y == 3 ? w2 : w3;
    int n4 = (y == 0 ? BSD : DD) >> 2;
    const float4* x4 = (const float4*)x;
    float m = 0.f;
    int stride = gridDim.x * blockDim.x;
    for (int i = blockIdx.x * blockDim.x + threadIdx.x; i < n4; i += stride) {
        float4 v = x4[i];
        m = fmaxf(m, fmaxf(fmaxf(fabsf(v.x), fabsf(v.y)), fmaxf(fabsf(v.z), fabsf(v.w))));
    }
    #pragma unroll
    for (int o = 16; o; o >>= 1) m = fmaxf(m, __shfl_xor_sync(0xffffffffu, m, o));
    __shared__ float sm[8];
    if ((threadIdx.x & 31) == 0) sm[threadIdx.x >> 5] = m;
    __syncthreads();
    if (threadIdx.x < 32) {
        m = (threadIdx.x < 8u) ? sm[threadIdx.x] : 0.f;
        #pragma unroll
        for (int o = 4; o; o >>= 1) m = fmaxf(m, __shfl_xor_sync(0xffffffffu, m, o));
        if (threadIdx.x == 0) atomicMax(&g_absmax[y], __float_as_uint(m));
    }
}

// ---------------- batched quantize: grid.y = 0 hidden, 1..4 weights ----------------
__global__ void quant_all_k(const float* __restrict__ h,
                            const float* w0, const float* w1,
                            const float* w2, const float* w3) {
    int y = blockIdx.y;
    const float* x = y == 0 ? h : y == 1 ? w0 : y == 2 ? w1 : y == 3 ? w2 : w3;
    __nv_bfloat16* out = y == 0 ? g_Xq : g_Wb[y - 1];
    int n4 = (y == 0 ? BSD : DD) >> 2;
    float s = fmaxf(__fdiv_rn(__uint_as_float(g_absmax[y]), 127.0f), 1e-8f);
    if (blockIdx.x == 0 && threadIdx.x == 0) g_scales[y] = s;
    int stride = gridDim.x * blockDim.x;
    for (int i = blockIdx.x * blockDim.x + threadIdx.x; i < n4; i += stride) {
        float4 v = ((const float4*)x)[i];
        __nv_bfloat162 lo = __floats2bfloat162_rn(rintf(__fdiv_rn(v.x, s)), rintf(__fdiv_rn(v.y, s)));
        __nv_bfloat162 hi = __floats2bfloat162_rn(rintf(__fdiv_rn(v.z, s)), rintf(__fdiv_rn(v.w, s)));
        uint2 pack;
        pack.x = *(unsigned*)&lo;
        pack.y = *(unsigned*)&hi;
        ((uint2*)out)[i] = pack;
    }
}

// ---------------- attn quantize (slot 5 -> g_Aq) ----------------
__global__ void quant_attn_k() {
    float s = fmaxf(__fdiv_rn(__uint_as_float(g_absmax[5]), 127.0f), 1e-8f);
    if (blockIdx.x == 0 && threadIdx.x == 0) g_scales[5] = s;
    int stride = gridDim.x * blockDim.x;
    for (int i = blockIdx.x * blockDim.x + threadIdx.x; i < (BSD >> 2); i += stride) {
        float4 v = ((const float4*)g_attn)[i];
        __nv_bfloat162 lo = __floats2bfloat162_rn(rintf(__fdiv_rn(v.x, s)), rintf(__fdiv_rn(v.y, s)));
        __nv_bfloat162 hi = __floats2bfloat162_rn(rintf(__fdiv_rn(v.z, s)), rintf(__fdiv_rn(v.w, s)));
        uint2 pack;
        pack.x = *(unsigned*)&lo;
        pack.y = *(unsigned*)&hi;
        ((uint2*)g_Aq)[i] = pack;
    }
}

// ================= pipelined bf16 GEMM core =================
#define BM2 128
#define BN2 64
#define BK2 32
#define PKB 80
#define STG_BYTES ((BM2 + BN2) * PKB)
#define KTILES (DIM / BK2)

// c_sel: 0 -> g_Q, 1 -> g_Khl, 2 -> g_Vhl, 3 -> cext
__device__ __forceinline__ void gemm_body(const __nv_bfloat16* __restrict__ A,
                                          const __nv_bfloat16* __restrict__ B,
                                          const float* __restrict__ bias,
                                          float* __restrict__ cext, int c_sel,
                                          float scale, char* sm2) {
    const int rb = blockIdx.y * BM2, cb = blockIdx.x * BN2;
    const int tid = threadIdx.x, wid = tid >> 5, lane = tid & 31;
    const unsigned sbase = (unsigned)__cvta_generic_to_shared(sm2);

    const int wm = wid & 3, wn = wid >> 2;
    const int a_row = wm * 32 + (lane & 7) + ((lane >> 3) & 1) * 8;
    const int a_koff = (lane >> 4) * 8;
    const int b_row = wn * 32 + (lane & 7) + (lane >> 4) * 8;
    const int b_koff = ((lane >> 3) & 1) * 8;

    float c[2][4][4];
    #pragma unroll
    for (int mt = 0; mt < 2; mt++)
        #pragma unroll
        for (int nt = 0; nt < 4; nt++)
            #pragma unroll
            for (int e = 0; e < 4; e++) c[mt][nt][e] = 0.f;

    auto issue = [&](int ki) {
        int kt = ki * BK2;
        unsigned s = sbase + (ki % 3) * STG_BYTES;
        #pragma unroll
        for (int r2 = 0; r2 < 2; r2++) {
            int cidx = tid + r2 * 256;
            int row = cidx >> 2, ch = cidx & 3;
            cpasync16(s + row * PKB + ch * 16, A + (size_t)(rb + row) * DIM + kt + ch * 8);
        }
        {
            int row = tid >> 2, ch = tid & 3;
            cpasync16(s + BM2 * PKB + row * PKB + ch * 16, B + (size_t)(cb + row) * DIM + kt + ch * 8);
        }
        CP_COMMIT;
    };

    issue(0);
    issue(1);

    for (int i = 0; i < KTILES; i++) {
        if (i + 1 < KTILES) { CP_WAIT(1); } else { CP_WAIT(0); }
        __syncthreads();
        if (i + 2 < KTILES) issue(i + 2);
        unsigned s = sbase + (i % 3) * STG_BYTES;
        #pragma unroll
        for (int ks = 0; ks < BK2; ks += 16) {
            unsigned af[2][4], bf[2][4];
            ldmat4(af[0], s + a_row * PKB + (ks + a_koff) * 2);
            ldmat4(af[1], s + (a_row + 16) * PKB + (ks + a_koff) * 2);
            ldmat4(bf[0], s + BM2 * PKB + b_row * PKB + (ks + b_koff) * 2);
            ldmat4(bf[1], s + BM2 * PKB + (b_row + 16) * PKB + (ks + b_koff) * 2);
            #pragma unroll
            for (int mt = 0; mt < 2; mt++)
                #pragma unroll
                for (int nt = 0; nt < 4; nt++)
                    mma16816(c[mt][nt], af[mt], &bf[nt >> 1][(nt & 1) * 2]);
        }
        __syncthreads();
    }

    const int g = lane >> 2, tig = lane & 3;
    #pragma unroll
    for (int mt = 0; mt < 2; mt++) {
        #pragma unroll
        for (int nt = 0; nt < 4; nt++) {
            int col = cb + wn * 32 + nt * 8 + 2 * tig;
            float2 bv = *(const float2*)&bias[col];
            #pragma unroll
            for (int half = 0; half < 2; half++) {
                int row = rb + wm * 32 + mt * 16 + g + half * 8;
                float x = c[mt][nt][half * 2]     * scale + bv.x;
                float y = c[mt][nt][half * 2 + 1] * scale + bv.y;
                size_t off = (size_t)row * DIM + col;
                if (c_sel == 0) {
                    *(float2*)&g_Q[off] = make_float2(x, y);
                } else if (c_sel == 1) {
                    float xh = __uint_as_float(f2t(x)), yh = __uint_as_float(f2t(y));
                    *(float4*)&g_Khl[2 * off] = make_float4(
                        xh, __uint_as_float(f2t(x - xh)),
                        yh, __uint_as_float(f2t(y - yh)));
                } else if (c_sel == 2) {
                    float xh = __uint_as_float(f2t(x)), yh = __uint_as_float(f2t(y));
                    *(float4*)&g_Vhl[2 * off] = make_float4(
                        xh, __uint_as_float(f2t(x - xh)),
                        yh, __uint_as_float(f2t(y - yh)));
                } else {
                    *(float2*)&cext[off] = make_float2(x, y);
                }
            }
        }
    }
}

// fused Q/K/V projection: grid.z selects weight + destination
__global__ void __launch_bounds__(256) gemm_qkv_k(const float* __restrict__ bq,
                                                  const float* __restrict__ bk,
                                                  const float* __restrict__ bv) {
    extern __shared__ char sm2[];
    int z = blockIdx.z;
    const float* bias = z == 0 ? bq : z == 1 ? bk : bv;
    float scale = g_scales[0] * g_scales[1 + z];
    gemm_body(g_Xq, g_Wb[z], bias, nullptr, z, scale, sm2);
}

// output projection
__global__ void __launch_bounds__(256) gemm_o_k(const float* __restrict__ bo,
                                                float* __restrict__ out) {
    extern __shared__ char sm2[];
    float scale = g_scales[5] * g_scales[4];
    gemm_body(g_Aq, g_Wb[3], bo, out, 3, scale, sm2);
}

// ================= tf32 3-term split flash attention =================
// BQ=64 (4 warps x 16 rows), BK=32, double-buffered K/V, 128 threads, 2 CTAs/SM.
#define QLD 72          /* Q staging row stride (floats) */
#define PLD 40          /* P staging row stride (floats) */
#define KLD 136         /* interleaved K/V smem row stride (floats) */
#define KBUF (32*KLD)   /* one K or V tile buffer (floats) = 4352 */

// smem float offsets
#define OFF_QP   0                          /* Q staging 64*72=4608, P staging 64*40 subset */
#define OFF_KHL  (64*QLD)                   /* 4608 */
#define OFF_VHL  (OFF_KHL + 2*KBUF)         /* 13312 */
#define OFF_MS   (OFF_VHL + 2*KBUF)         /* 22016: 2 x 32 mask */
#define OFF_SRED (OFF_MS + 64)              /* 22080 */
#define SMF_TOT  (OFF_SRED + 4)             /* 22084 floats = 88336 B */

#define NTILES (SS / 32)    /* 64 */

__global__ void __launch_bounds__(128) attn_k(const float* __restrict__ mask) {
    extern __shared__ float smf[];
    float* QPs  = smf + OFF_QP;
    float* Khl  = smf + OFF_KHL;
    float* Vhl  = smf + OFF_VHL;
    float* Msd  = smf + OFF_MS;
    float* sred = smf + OFF_SRED;

    const int b = blockIdx.z, h = blockIdx.y;
    const int q0 = blockIdx.x * 64;
    const int tid = threadIdx.x;
    const int wid = tid >> 5, lane = tid & 31;
    const int g = lane >> 2, tig = lane & 3;
    const size_t base = (size_t)b * SS * DIM + (size_t)h * HD;

    const unsigned sb = (unsigned)__cvta_generic_to_shared(smf);
    const unsigned sKhl = sb + OFF_KHL * 4;
    const unsigned sVhl = sb + OFF_VHL * 4;
    const unsigned sMs  = sb + OFF_MS * 4;

    // ---- stage Q tile (64 x 64) ----
    for (int i = tid; i < 64 * 16; i += 128) {
        int r = i >> 4, c4 = (i & 15) << 2;
        *(float4*)&QPs[r * QLD + c4] = *(const float4*)&g_Q[base + (size_t)(q0 + r) * DIM + c4];
    }
    __syncthreads();

    // ---- preload Q A-fragments (tf32 hi/lo), 0.125 folded in ----
    unsigned qh[8][4], ql[8][4];
    {
        const float* Q0 = QPs + (wid * 16 + g) * QLD + tig;
        #pragma unroll
        for (int k8 = 0; k8 < 8; k8++) {
            float a[4];
            a[0] = Q0[k8 * 8] * 0.125f;
            a[1] = Q0[8 * QLD + k8 * 8] * 0.125f;
            a[2] = Q0[k8 * 8 + 4] * 0.125f;
            a[3] = Q0[8 * QLD + k8 * 8 + 4] * 0.125f;
            #pragma unroll
            for (int e = 0; e < 4; e++) {
                qh[k8][e] = f2t(a[e]);
                ql[k8][e] = f2t(a[e] - __uint_as_float(qh[k8][e]));
            }
        }
    }
    __syncthreads();   // Q frag reads done before QPs reused for P

    float m0 = -1e30f, m8 = -1e30f, l0 = 0.f, l8 = 0.f;
    float o[8][4];
    #pragma unroll
    for (int n = 0; n < 8; n++)
        #pragma unroll
        for (int e = 0; e < 4; e++) o[n][e] = 0.f;

    // tile loader: 32 K rows + 32 V rows of 128 interleaved floats (512B each)
    auto issue_tile = [&](int kt, int buf) {
        const char* gK = (const char*)&g_Khl[2 * (base + (size_t)kt * DIM)];
        const char* gV = (const char*)&g_Vhl[2 * (base + (size_t)kt * DIM)];
        unsigned dK = sKhl + buf * (KBUF * 4);
        unsigned dV = sVhl + buf * (KBUF * 4);
        #pragma unroll
        for (int c = 0; c < 8; c++) {
            int cidx = tid + c * 128;
            int r = cidx >> 5, ch = cidx & 31;
            cpasync16(dK + r * (KLD * 4) + ch * 16, gK + (size_t)r * (2 * DIM * 4) + ch * 16);
            cpasync16(dV + r * (KLD * 4) + ch * 16, gV + (size_t)r * (2 * DIM * 4) + ch * 16);
        }
        if (tid < 8)
            cpasync16(sMs + buf * 128 + tid * 16,
                      (const char*)&mask[(size_t)b * SS + kt] + tid * 16);
        CP_COMMIT;
    };

    issue_tile(0, 0);

    for (int it = 0; it < NTILES; it++) {
        const int cur = it & 1;
        CP_WAIT(0);
        __syncthreads();     // buffer cur ready; all warps done with buffer 1-cur
        if (it + 1 < NTILES) issue_tile((it + 1) * 32, 1 - cur);

        const float* Kc = Khl + cur * KBUF;
        const float* Vc = Vhl + cur * KBUF;
        const float* Mc = Msd + cur * 32;

        // ---- S = (Q/8) K^T : 4 n-cols of 8 keys each ----
        float s[4][4];
        #pragma unroll
        for (int n = 0; n < 4; n++)
            #pragma unroll
            for (int e = 0; e < 4; e++) s[n][e] = 0.f;

        #pragma unroll
        for (int k8 = 0; k8 < 8; k8++) {
            #pragma unroll
            for (int n = 0; n < 4; n++) {
                float2 b0 = *(const float2*)&Kc[(n * 8 + g) * KLD + 16 * k8 + 2 * tig];
                float2 b1 = *(const float2*)&Kc[(n * 8 + g) * KLD + 16 * k8 + 2 * tig + 8];
                MMA8(s[n], qh[k8], __float_as_uint(b0.x), __float_as_uint(b1.x));
                MMA8(s[n], qh[k8], __float_as_uint(b0.y), __float_as_uint(b1.y));
                MMA8(s[n], ql[k8], __float_as_uint(b0.x), __float_as_uint(b1.x));
            }
        }

        // ---- online softmax ----
        float mx0 = -1e30f, mx8 = -1e30f;
        #pragma unroll
        for (int n = 0; n < 4; n++) {
            float2 mm = *(const float2*)&Mc[n * 8 + 2 * tig];
            float bx = mm.x * 10000.0f - 10000.0f;
            float by = mm.y * 10000.0f - 10000.0f;
            s[n][0] += bx;
            s[n][1] += by;
            s[n][2] += bx;
            s[n][3] += by;
            mx0 = fmaxf(mx0, fmaxf(s[n][0], s[n][1]));
            mx8 = fmaxf(mx8, fmaxf(s[n][2], s[n][3]));
        }
        mx0 = fmaxf(mx0, __shfl_xor_sync(0xffffffffu, mx0, 1));
        mx0 = fmaxf(mx0, __shfl_xor_sync(0xffffffffu, mx0, 2));
        mx8 = fmaxf(mx8, __shfl_xor_sync(0xffffffffu, mx8, 1));
        mx8 = fmaxf(mx8, __shfl_xor_sync(0xffffffffu, mx8, 2));

        float mn0 = fmaxf(m0, mx0), mn8 = fmaxf(m8, mx8);
        float c0 = __expf(m0 - mn0), c8 = __expf(m8 - mn8);
        float sum0 = 0.f, sum8 = 0.f;
        #pragma unroll
        for (int n = 0; n < 4; n++) {
            s[n][0] = __expf(s[n][0] - mn0); sum0 += s[n][0];
            s[n][1] = __expf(s[n][1] - mn0); sum0 += s[n][1];
            s[n][2] = __expf(s[n][2] - mn8); sum8 += s[n][2];
            s[n][3] = __expf(s[n][3] - mn8); sum8 += s[n][3];
        }
        sum0 += __shfl_xor_sync(0xffffffffu, sum0, 1);
        sum0 += __shfl_xor_sync(0xffffffffu, sum0, 2);
        sum8 += __shfl_xor_sync(0xffffffffu, sum8, 1);
        sum8 += __shfl_xor_sync(0xffffffffu, sum8, 2);
        l0 = l0 * c0 + sum0;
        l8 = l8 * c8 + sum8;
        m0 = mn0; m8 = mn8;

        #pragma unroll
        for (int n = 0; n < 8; n++) {
            o[n][0] *= c0; o[n][1] *= c0;
            o[n][2] *= c8; o[n][3] *= c8;
        }

        // ---- write P (warp-private slice of QPs) ----
        {
            float* pw = &QPs[(wid * 16 + g) * PLD + 2 * tig];
            #pragma unroll
            for (int n = 0; n < 4; n++) {
                *(float2*)&pw[n * 8] = make_float2(s[n][0], s[n][1]);
                *(float2*)&pw[8 * PLD + n * 8] = make_float2(s[n][2], s[n][3]);
            }
        }
        __syncwarp();

        // ---- O += P V (3-term tf32 split) ----
        {
            const float* pr = &QPs[(wid * 16 + g) * PLD + tig];
            #pragma unroll
            for (int k8 = 0; k8 < 4; k8++) {
                float a[4];
                a[0] = pr[k8 * 8];
                a[1] = pr[8 * PLD + k8 * 8];
                a[2] = pr[k8 * 8 + 4];
                a[3] = pr[8 * PLD + k8 * 8 + 4];
                unsigned ph[4], pl[4];
                #pragma unroll
                for (int e = 0; e < 4; e++) {
                    ph[e] = f2t(a[e]);
                    pl[e] = f2t(a[e] - __uint_as_float(ph[e]));
                }
                #pragma unroll
                for (int n = 0; n < 8; n++) {
                    float2 v0 = *(const float2*)&Vc[(8 * k8 + tig) * KLD + 16 * n + 2 * g];
                    float2 v1 = *(const float2*)&Vc[(8 * k8 + tig + 4) * KLD + 16 * n + 2 * g];
                    MMA8(o[n], ph, __float_as_uint(v0.x), __float_as_uint(v1.x));
                    MMA8(o[n], ph, __float_as_uint(v0.y), __float_as_uint(v1.y));
                    MMA8(o[n], pl, __float_as_uint(v0.x), __float_as_uint(v1.x));
                }
            }
        }
    }

    // ---- epilogue: normalize, store, fused absmax ----
    float inv0 = __fdiv_rn(1.0f, l0);
    float inv8 = __fdiv_rn(1.0f, l8);
    int qg = q0 + wid * 16 + g;
    float amax = 0.f;
    #pragma unroll
    for (int n = 0; n < 8; n++) {
        float x0 = o[n][0] * inv0, y0 = o[n][1] * inv0;
        float x8 = o[n][2] * inv8, y8 = o[n][3] * inv8;
        amax = fmaxf(amax, fmaxf(fmaxf(fabsf(x0), fabsf(y0)), fmaxf(fabsf(x8), fabsf(y8))));
        *(float2*)&g_attn[base + (size_t)qg * DIM + n * 8 + 2 * tig] = make_float2(x0, y0);
        *(float2*)&g_attn[base + (size_t)(qg + 8) * DIM + n * 8 + 2 * tig] = make_float2(x8, y8);
    }
    #pragma unroll
    for (int off = 16; off; off >>= 1) amax = fmaxf(amax, __shfl_xor_sync(0xffffffffu, amax, off));
    if (lane == 0) sred[wid] = amax;
    __syncthreads();
    if (tid == 0) {
        float m = fmaxf(fmaxf(sred[0], sred[1]), fmaxf(sred[2], sred[3]));
        atomicMax(&g_absmax[5], __float_as_uint(m));
    }
}

// ---------------- launch ----------------
extern "C" void kernel_launch(void* const* d_in, const int* in_sizes, int n_in,
                              void* d_out, int out_size) {
    const float* hidden = (const float*)d_in[0];
    const float* mask   = (const float*)d_in[1];
    const float* Wq = (const float*)d_in[2];
    const float* bq = (const float*)d_in[3];
    const float* Wk = (const float*)d_in[4];
    const float* bk = (const float*)d_in[5];
    const float* Wv = (const float*)d_in[6];
    const float* bv = (const float*)d_in[7];
    const float* Wo = (const float*)d_in[8];
    const float* bo = (const float*)d_in[9];
    float* out = (float*)d_out;

    const int ATTN_SMEM = SMF_TOT * 4;   // 88336 bytes -> 2 CTAs/SM
    cudaFuncSetAttribute(attn_k, cudaFuncAttributeMaxDynamicSharedMemorySize, ATTN_SMEM);
    const int GEMM_SMEM = 3 * STG_BYTES;

    absmax_all_k<<<dim3(256, 5), 256>>>(hidden, Wq, Wk, Wv, Wo);            // 1
    quant_all_k<<<dim3(256, 5), 256>>>(hidden, Wq, Wk, Wv, Wo);             // 2
    gemm_qkv_k<<<dim3(DIM / BN2, (BB * SS) / BM2, 3), 256, GEMM_SMEM>>>(bq, bk, bv); // 3
    attn_k<<<dim3(SS / 64, HH, BB), 128, ATTN_SMEM>>>(mask);                // 4 <- ncu capture slot
    quant_attn_k<<<1024, 256>>>();                                          // 5
    gemm_o_k<<<dim3(DIM / BN2, (BB * SS) / BM2), 256, GEMM_SMEM>>>(bo, out); // 6
}

// round 8
// speedup vs baseline: 1.9270x; 1.9270x over previous
#include <cuda_runtime.h>
#include <cuda_bf16.h>
#include <cuda_fp16.h>

#define BB 2
#define SS 2048
#define DIM 1024
#define HH 16
#define HD 64
#define BSD (BB*SS*DIM)
#define DD  (DIM*DIM)

// ---------------- scratch ----------------
__device__ unsigned g_absmax[8];
__device__ float g_scales[8];
__device__ __align__(256) __nv_bfloat16 g_Xq[BSD];
__device__ __align__(256) __nv_bfloat16 g_Aq[BSD];
__device__ __align__(256) __nv_bfloat16 g_Wb[4][DD];
__device__ __align__(256) float g_Q[BSD];
__device__ __align__(256) __half g_Khi[BSD];   // [token][d] fp16 hi
__device__ __align__(256) __half g_Klo[BSD];   // [token][d] fp16 lo
__device__ __align__(256) __half g_VThi[BSD];  // [b,h][d][token] fp16 hi (transposed)
__device__ __align__(256) __half g_VTlo[BSD];
__device__ __align__(256) float g_attn[BSD];

// ---------------- helpers ----------------
__device__ __forceinline__ void cpasync16(unsigned saddr, const void* g) {
    asm volatile("cp.async.cg.shared.global [%0], [%1], 16;" :: "r"(saddr), "l"(g));
}
#define CP_COMMIT asm volatile("cp.async.commit_group;")
#define CP_WAIT(n) asm volatile("cp.async.wait_group %0;" :: "n"(n))

__device__ __forceinline__ void ldmat4(unsigned* r, unsigned addr) {
    asm volatile("ldmatrix.sync.aligned.m8n8.x4.shared.b16 {%0,%1,%2,%3},[%4];"
        : "=r"(r[0]), "=r"(r[1]), "=r"(r[2]), "=r"(r[3]) : "r"(addr));
}
__device__ __forceinline__ void mma16816(float* c, const unsigned* a, const unsigned* b) {
    asm volatile("mma.sync.aligned.m16n8k16.row.col.f32.bf16.bf16.f32 "
        "{%0,%1,%2,%3},{%4,%5,%6,%7},{%8,%9},{%0,%1,%2,%3};"
        : "+f"(c[0]), "+f"(c[1]), "+f"(c[2]), "+f"(c[3])
        : "r"(a[0]), "r"(a[1]), "r"(a[2]), "r"(a[3]), "r"(b[0]), "r"(b[1]));
}
// fp16 MMA, fp32 accumulate
#define MMAH(c, a, b0, b1) \
  asm volatile("mma.sync.aligned.m16n8k16.row.col.f32.f16.f16.f32 " \
    "{%0,%1,%2,%3},{%4,%5,%6,%7},{%8,%9},{%0,%1,%2,%3};" \
    : "+f"(c[0]), "+f"(c[1]), "+f"(c[2]), "+f"(c[3]) \
    : "r"(a[0]), "r"(a[1]), "r"(a[2]), "r"(a[3]), "r"(b0), "r"(b1))

// split (x,y) into packed fp16 hi/lo half2 pairs (Dekker: hi 11 bits, lo 11 bits)
__device__ __forceinline__ unsigned sp_split(float x, float y, unsigned& lo) {
    __half hx = __float2half_rn(x), hy = __float2half_rn(y);
    __half lx = __float2half_rn(x - __half2float(hx));
    __half ly = __float2half_rn(y - __half2float(hy));
    __half2 H = __halves2half2(hx, hy), L = __halves2half2(lx, ly);
    lo = *(unsigned*)&L;
    return *(unsigned*)&H;
}

// ---------------- batched absmax: grid.y = 0 hidden, 1..4 weights ----------------
__global__ void absmax_all_k(const float* __restrict__ h,
                             const float* w0, const float* w1,
                             const float* w2, const float* w3) {
    int y = blockIdx.y;
    const float* x = y == 0 ? h : y == 1 ? w0 : y == 2 ? w1 : y == 3 ? w2 : w3;
    int n4 = (y == 0 ? BSD : DD) >> 2;
    const float4* x4 = (const float4*)x;
    float m = 0.f;
    int stride = gridDim.x * blockDim.x;
    for (int i = blockIdx.x * blockDim.x + threadIdx.x; i < n4; i += stride) {
        float4 v = x4[i];
        m = fmaxf(m, fmaxf(fmaxf(fabsf(v.x), fabsf(v.y)), fmaxf(fabsf(v.z), fabsf(v.w))));
    }
    #pragma unroll
    for (int o = 16; o; o >>= 1) m = fmaxf(m, __shfl_xor_sync(0xffffffffu, m, o));
    __shared__ float sm[8];
    if ((threadIdx.x & 31) == 0) sm[threadIdx.x >> 5] = m;
    __syncthreads();
    if (threadIdx.x < 32) {
        m = (threadIdx.x < 8u) ? sm[threadIdx.x] : 0.f;
        #pragma unroll
        for (int o = 4; o; o >>= 1) m = fmaxf(m, __shfl_xor_sync(0xffffffffu, m, o));
        if (threadIdx.x == 0) atomicMax(&g_absmax[y], __float_as_uint(m));
    }
}

// ---------------- batched quantize: grid.y = 0 hidden, 1..4 weights ----------------
__global__ void quant_all_k(const float* __restrict__ h,
                            const float* w0, const float* w1,
                            const float* w2, const float* w3) {
    int y = blockIdx.y;
    const float* x = y == 0 ? h : y == 1 ? w0 : y == 2 ? w1 : y == 3 ? w2 : w3;
    __nv_bfloat16* out = y == 0 ? g_Xq : g_Wb[y - 1];
    int n4 = (y == 0 ? BSD : DD) >> 2;
    float s = fmaxf(__fdiv_rn(__uint_as_float(g_absmax[y]), 127.0f), 1e-8f);
    if (blockIdx.x == 0 && threadIdx.x == 0) g_scales[y] = s;
    int stride = gridDim.x * blockDim.x;
    for (int i = blockIdx.x * blockDim.x + threadIdx.x; i < n4; i += stride) {
        float4 v = ((const float4*)x)[i];
        __nv_bfloat162 lo = __floats2bfloat162_rn(rintf(__fdiv_rn(v.x, s)), rintf(__fdiv_rn(v.y, s)));
        __nv_bfloat162 hi = __floats2bfloat162_rn(rintf(__fdiv_rn(v.z, s)), rintf(__fdiv_rn(v.w, s)));
        uint2 pack;
        pack.x = *(unsigned*)&lo;
        pack.y = *(unsigned*)&hi;
        ((uint2*)out)[i] = pack;
    }
}

// ---------------- attn quantize (slot 5 -> g_Aq) ----------------
__global__ void quant_attn_k() {
    float s = fmaxf(__fdiv_rn(__uint_as_float(g_absmax[5]), 127.0f), 1e-8f);
    if (blockIdx.x == 0 && threadIdx.x == 0) g_scales[5] = s;
    int stride = gridDim.x * blockDim.x;
    for (int i = blockIdx.x * blockDim.x + threadIdx.x; i < (BSD >> 2); i += stride) {
        float4 v = ((const float4*)g_attn)[i];
        __nv_bfloat162 lo = __floats2bfloat162_rn(rintf(__fdiv_rn(v.x, s)), rintf(__fdiv_rn(v.y, s)));
        __nv_bfloat162 hi = __floats2bfloat162_rn(rintf(__fdiv_rn(v.z, s)), rintf(__fdiv_rn(v.w, s)));
        uint2 pack;
        pack.x = *(unsigned*)&lo;
        pack.y = *(unsigned*)&hi;
        ((uint2*)g_Aq)[i] = pack;
    }
}

// ================= pipelined bf16 GEMM core =================
#define BM2 128
#define BN2 64
#define BK2 32
#define PKB 80
#define STG_BYTES ((BM2 + BN2) * PKB)
#define KTILES (DIM / BK2)

// c_sel: 0 -> g_Q(f32), 1 -> g_Khi/Klo(f16), 2 -> g_VThi/VTlo(f16,transposed), 3 -> cext
__device__ __forceinline__ void gemm_body(const __nv_bfloat16* __restrict__ A,
                                          const __nv_bfloat16* __restrict__ B,
                                          const float* __restrict__ bias,
                                          float* __restrict__ cext, int c_sel,
                                          float scale, char* sm2) {
    const int rb = blockIdx.y * BM2, cb = blockIdx.x * BN2;
    const int tid = threadIdx.x, wid = tid >> 5, lane = tid & 31;
    const unsigned sbase = (unsigned)__cvta_generic_to_shared(sm2);

    const int wm = wid & 3, wn = wid >> 2;
    const int a_row = wm * 32 + (lane & 7) + ((lane >> 3) & 1) * 8;
    const int a_koff = (lane >> 4) * 8;
    const int b_row = wn * 32 + (lane & 7) + (lane >> 4) * 8;
    const int b_koff = ((lane >> 3) & 1) * 8;

    float c[2][4][4];
    #pragma unroll
    for (int mt = 0; mt < 2; mt++)
        #pragma unroll
        for (int nt = 0; nt < 4; nt++)
            #pragma unroll
            for (int e = 0; e < 4; e++) c[mt][nt][e] = 0.f;

    auto issue = [&](int ki) {
        int kt = ki * BK2;
        unsigned s = sbase + (ki % 3) * STG_BYTES;
        #pragma unroll
        for (int r2 = 0; r2 < 2; r2++) {
            int cidx = tid + r2 * 256;
            int row = cidx >> 2, ch = cidx & 3;
            cpasync16(s + row * PKB + ch * 16, A + (size_t)(rb + row) * DIM + kt + ch * 8);
        }
        {
            int row = tid >> 2, ch = tid & 3;
            cpasync16(s + BM2 * PKB + row * PKB + ch * 16, B + (size_t)(cb + row) * DIM + kt + ch * 8);
        }
        CP_COMMIT;
    };

    issue(0);
    issue(1);

    for (int i = 0; i < KTILES; i++) {
        if (i + 1 < KTILES) { CP_WAIT(1); } else { CP_WAIT(0); }
        __syncthreads();
        if (i + 2 < KTILES) issue(i + 2);
        unsigned s = sbase + (i % 3) * STG_BYTES;
        #pragma unroll
        for (int ks = 0; ks < BK2; ks += 16) {
            unsigned af[2][4], bf[2][4];
            ldmat4(af[0], s + a_row * PKB + (ks + a_koff) * 2);
            ldmat4(af[1], s + (a_row + 16) * PKB + (ks + a_koff) * 2);
            ldmat4(bf[0], s + BM2 * PKB + b_row * PKB + (ks + b_koff) * 2);
            ldmat4(bf[1], s + BM2 * PKB + (b_row + 16) * PKB + (ks + b_koff) * 2);
            #pragma unroll
            for (int mt = 0; mt < 2; mt++)
                #pragma unroll
                for (int nt = 0; nt < 4; nt++)
                    mma16816(c[mt][nt], af[mt], &bf[nt >> 1][(nt & 1) * 2]);
        }
        __syncthreads();
    }

    const int g = lane >> 2, tig = lane & 3;
    #pragma unroll
    for (int mt = 0; mt < 2; mt++) {
        #pragma unroll
        for (int nt = 0; nt < 4; nt++) {
            int col = cb + wn * 32 + nt * 8 + 2 * tig;
            float2 bv = *(const float2*)&bias[col];
            #pragma unroll
            for (int half = 0; half < 2; half++) {
                int row = rb + wm * 32 + mt * 16 + g + half * 8;
                float x = c[mt][nt][half * 2]     * scale + bv.x;
                float y = c[mt][nt][half * 2 + 1] * scale + bv.y;
                size_t off = (size_t)row * DIM + col;
                if (c_sel == 0) {
                    *(float2*)&g_Q[off] = make_float2(x, y);
                } else if (c_sel == 1) {
                    unsigned lo, hi = sp_split(x, y, lo);
                    *(unsigned*)&g_Khi[off] = hi;
                    *(unsigned*)&g_Klo[off] = lo;
                } else if (c_sel == 2) {
                    __half hx = __float2half_rn(x), hy = __float2half_rn(y);
                    __half lx = __float2half_rn(x - __half2float(hx));
                    __half ly = __float2half_rn(y - __half2float(hy));
                    int brow = row >> 11, tok = row & (SS - 1);
                    int hh = col >> 6, dd = col & 63;
                    size_t offT = ((size_t)((brow * HH + hh) * HD + dd)) * SS + tok;
                    g_VThi[offT] = hx;      g_VTlo[offT] = lx;
                    g_VThi[offT + SS] = hy; g_VTlo[offT + SS] = ly;
                } else {
                    *(float2*)&cext[off] = make_float2(x, y);
                }
            }
        }
    }
}

__global__ void __launch_bounds__(256) gemm_qkv_k(const float* __restrict__ bq,
                                                  const float* __restrict__ bk,
                                                  const float* __restrict__ bv) {
    extern __shared__ char sm2[];
    int z = blockIdx.z;
    const float* bias = z == 0 ? bq : z == 1 ? bk : bv;
    float scale = g_scales[0] * g_scales[1 + z];
    gemm_body(g_Xq, g_Wb[z], bias, nullptr, z, scale, sm2);
}

__global__ void __launch_bounds__(256) gemm_o_k(const float* __restrict__ bo,
                                                float* __restrict__ out) {
    extern __shared__ char sm2[];
    float scale = g_scales[5] * g_scales[4];
    gemm_body(g_Aq, g_Wb[3], bo, out, 3, scale, sm2);
}

// ================= fp16 3-term split flash attention =================
// BQ=128 (8 warps x 16 rows), BK=64, fp16 hi/lo Dekker operands, double-buffered,
// 256 threads, 2 CTAs/SM. All smem rows stride 144B -> conflict-free patterns.
#define QROWF 72        /* Q staging row stride (floats) */
#define PROWU 36        /* P row stride in 4B units (72 halves = 144B) */
#define KROWB 144       /* K/V smem row stride bytes */
#define PLANEB 9216     /* one 64-row f16 plane: 64*144 */
#define PLANEU 2304     /* same in 4B units */

// smem byte offsets
#define OB_P    0               /* Phi [128][144B]; Plo at +18432. Q staging f32 reuses [0,36864) */
#define OB_PLO  18432
#define OB_K    36864           /* per buf 18432 (Khi 9216 + Klo 9216); 2 bufs */
#define OB_V    73728
#define OB_MS   110592          /* 2 x 256B mask */
#define OB_SRED 111104
#define SMEM_ATTN 111136

__global__ void __launch_bounds__(256, 2) attn_k(const float* __restrict__ mask) {
    extern __shared__ char smc[];
    float* smf = (float*)smc;

    const int b = blockIdx.z, h = blockIdx.y;
    const int q0 = blockIdx.x * 128;
    const int tid = threadIdx.x;
    const int wid = tid >> 5, lane = tid & 31;
    const int g = lane >> 2, tig = lane & 3;
    const size_t base = (size_t)b * SS * DIM + (size_t)h * HD;          // Q/K [token][d]
    const size_t baseT = (size_t)(b * HH + h) * HD * SS;                // V^T [d][token]

    const unsigned sb = (unsigned)__cvta_generic_to_shared(smc);

    // ---- stage Q tile (f32) into [0, 36864) ----
    for (int i = tid; i < 128 * 16; i += 256) {
        int r = i >> 4, c4 = (i & 15) << 2;
        *(float4*)&smf[r * QROWF + c4] = *(const float4*)&g_Q[base + (size_t)(q0 + r) * DIM + c4];
    }
    __syncthreads();

    // ---- Q fragments: fp16 hi/lo packed half2, 0.125 folded ----
    unsigned qh[4][4], ql[4][4];
    {
        const float* Q0 = smf + (wid * 16 + g) * QROWF;
        #pragma unroll
        for (int kg = 0; kg < 4; kg++) {
            float2 v00 = *(const float2*)&Q0[kg * 16 + 2 * tig];
            float2 v10 = *(const float2*)&Q0[8 * QROWF + kg * 16 + 2 * tig];
            float2 v01 = *(const float2*)&Q0[kg * 16 + 2 * tig + 8];
            float2 v11 = *(const float2*)&Q0[8 * QROWF + kg * 16 + 2 * tig + 8];
            qh[kg][0] = sp_split(v00.x * 0.125f, v00.y * 0.125f, ql[kg][0]);
            qh[kg][1] = sp_split(v10.x * 0.125f, v10.y * 0.125f, ql[kg][1]);
            qh[kg][2] = sp_split(v01.x * 0.125f, v01.y * 0.125f, ql[kg][2]);
            qh[kg][3] = sp_split(v11.x * 0.125f, v11.y * 0.125f, ql[kg][3]);
        }
    }
    __syncthreads();   // Q reads done before P region reused

    float m0 = -1e30f, m8 = -1e30f, l0 = 0.f, l8 = 0.f;
    float o[8][4];
    #pragma unroll
    for (int n = 0; n < 8; n++)
        #pragma unroll
        for (int e = 0; e < 4; e++) o[n][e] = 0.f;

    // tile loader: 4 f16 planes x 64 rows x 128B
    auto issue_tile = [&](int kt, int buf) {
        const char* gKh = (const char*)&g_Khi[base + (size_t)kt * DIM];
        const char* gKl = (const char*)&g_Klo[base + (size_t)kt * DIM];
        const char* gVh = (const char*)&g_VThi[baseT + kt];
        const char* gVl = (const char*)&g_VTlo[baseT + kt];
        unsigned dK = sb + OB_K + buf * 18432;
        unsigned dV = sb + OB_V + buf * 18432;
        #pragma unroll
        for (int c = 0; c < 2; c++) {
            int idx = tid + c * 256;
            int r = idx >> 3, ch = idx & 7;
            cpasync16(dK + r * KROWB + ch * 16,          gKh + (size_t)r * (DIM * 2) + ch * 16);
            cpasync16(dK + PLANEB + r * KROWB + ch * 16, gKl + (size_t)r * (DIM * 2) + ch * 16);
            cpasync16(dV + r * KROWB + ch * 16,          gVh + (size_t)r * (SS * 2) + ch * 16);
            cpasync16(dV + PLANEB + r * KROWB + ch * 16, gVl + (size_t)r * (SS * 2) + ch * 16);
        }
        if (tid < 16)
            cpasync16(sb + OB_MS + buf * 256 + tid * 16,
                      (const char*)&mask[(size_t)b * SS + kt] + tid * 16);
        CP_COMMIT;
    };

    issue_tile(0, 0);

    for (int it = 0; it < SS / 64; it++) {
        const int cur = it & 1;
        CP_WAIT(0);
        __syncthreads();
        if (it + 1 < SS / 64) issue_tile((it + 1) * 64, 1 - cur);

        const unsigned* Kf = (const unsigned*)(smc + OB_K + cur * 18432);
        const unsigned* Vf = (const unsigned*)(smc + OB_V + cur * 18432);
        const float* Mc = (const float*)(smc + OB_MS + cur * 256);

        // ---- S = (Q/8) K^T : fp16 3-term ----
        float s[8][4];
        #pragma unroll
        for (int n = 0; n < 8; n++)
            #pragma unroll
            for (int e = 0; e < 4; e++) s[n][e] = 0.f;

        #pragma unroll
        for (int kg = 0; kg < 4; kg++) {
            #pragma unroll
            for (int n = 0; n < 8; n++) {
                const unsigned* kp = Kf + (n * 8 + g) * PROWU + kg * 8 + tig;
                unsigned bh0 = kp[0], bh1 = kp[4];
                unsigned bl0 = kp[PLANEU], bl1 = kp[PLANEU + 4];
                MMAH(s[n], qh[kg], bh0, bh1);
                MMAH(s[n], ql[kg], bh0, bh1);
                MMAH(s[n], qh[kg], bl0, bl1);
            }
        }

        // ---- online softmax ----
        float mx0 = -1e30f, mx8 = -1e30f;
        #pragma unroll
        for (int n = 0; n < 8; n++) {
            float2 mm = *(const float2*)&Mc[n * 8 + 2 * tig];
            float bx = mm.x * 10000.0f - 10000.0f;
            float by = mm.y * 10000.0f - 10000.0f;
            s[n][0] += bx; s[n][1] += by;
            s[n][2] += bx; s[n][3] += by;
            mx0 = fmaxf(mx0, fmaxf(s[n][0], s[n][1]));
            mx8 = fmaxf(mx8, fmaxf(s[n][2], s[n][3]));
        }
        mx0 = fmaxf(mx0, __shfl_xor_sync(0xffffffffu, mx0, 1));
        mx0 = fmaxf(mx0, __shfl_xor_sync(0xffffffffu, mx0, 2));
        mx8 = fmaxf(mx8, __shfl_xor_sync(0xffffffffu, mx8, 1));
        mx8 = fmaxf(mx8, __shfl_xor_sync(0xffffffffu, mx8, 2));

        float mn0 = fmaxf(m0, mx0), mn8 = fmaxf(m8, mx8);
        float c0 = __expf(m0 - mn0), c8 = __expf(m8 - mn8);
        float sum0 = 0.f, sum8 = 0.f;
        #pragma unroll
        for (int n = 0; n < 8; n++) {
            s[n][0] = __expf(s[n][0] - mn0); sum0 += s[n][0];
            s[n][1] = __expf(s[n][1] - mn0); sum0 += s[n][1];
            s[n][2] = __expf(s[n][2] - mn8); sum8 += s[n][2];
            s[n][3] = __expf(s[n][3] - mn8); sum8 += s[n][3];
        }
        sum0 += __shfl_xor_sync(0xffffffffu, sum0, 1);
        sum0 += __shfl_xor_sync(0xffffffffu, sum0, 2);
        sum8 += __shfl_xor_sync(0xffffffffu, sum8, 1);
        sum8 += __shfl_xor_sync(0xffffffffu, sum8, 2);
        l0 = l0 * c0 + sum0;
        l8 = l8 * c8 + sum8;
        m0 = mn0; m8 = mn8;

        #pragma unroll
        for (int n = 0; n < 8; n++) {
            o[n][0] *= c0; o[n][1] *= c0;
            o[n][2] *= c8; o[n][3] *= c8;
        }

        // ---- split P to fp16 hi/lo planes (warp-private rows) ----
        {
            unsigned* Ph = (unsigned*)(smc + OB_P)   + (wid * 16 + g) * PROWU + tig;
            unsigned* Pl = (unsigned*)(smc + OB_PLO) + (wid * 16 + g) * PROWU + tig;
            #pragma unroll
            for (int n = 0; n < 8; n++) {
                unsigned lo0, lo1;
                unsigned hi0 = sp_split(s[n][0], s[n][1], lo0);
                unsigned hi1 = sp_split(s[n][2], s[n][3], lo1);
                Ph[n * 4] = hi0;               Pl[n * 4] = lo0;
                Ph[8 * PROWU + n * 4] = hi1;   Pl[8 * PROWU + n * 4] = lo1;
            }
        }
        __syncwarp();

        // ---- O += P V : fp16 3-term ----
        #pragma unroll
        for (int kg = 0; kg < 4; kg++) {
            const unsigned* ph = (const unsigned*)(smc + OB_P)   + (wid * 16 + g) * PROWU + kg * 8 + tig;
            const unsigned* pl = (const unsigned*)(smc + OB_PLO) + (wid * 16 + g) * PROWU + kg * 8 + tig;
            unsigned ah[4] = { ph[0], ph[8 * PROWU], ph[4], ph[8 * PROWU + 4] };
            unsigned al[4] = { pl[0], pl[8 * PROWU], pl[4], pl[8 * PROWU + 4] };
            #pragma unroll
            for (int n = 0; n < 8; n++) {
                const unsigned* vp = Vf + (n * 8 + g) * PROWU + kg * 8 + tig;
                unsigned bh0 = vp[0], bh1 = vp[4];
                unsigned bl0 = vp[PLANEU], bl1 = vp[PLANEU + 4];
                MMAH(o[n], ah, bh0, bh1);
                MMAH(o[n], al, bh0, bh1);
                MMAH(o[n], ah, bl0, bl1);
            }
        }
    }

    // ---- epilogue: normalize, store, fused absmax ----
    float inv0 = __fdiv_rn(1.0f, l0);
    float inv8 = __fdiv_rn(1.0f, l8);
    int qg = q0 + wid * 16 + g;
    float amax = 0.f;
    #pragma unroll
    for (int n = 0; n < 8; n++) {
        float x0 = o[n][0] * inv0, y0 = o[n][1] * inv0;
        float x8 = o[n][2] * inv8, y8 = o[n][3] * inv8;
        amax = fmaxf(amax, fmaxf(fmaxf(fabsf(x0), fabsf(y0)), fmaxf(fabsf(x8), fabsf(y8))));
        *(float2*)&g_attn[base + (size_t)qg * DIM + n * 8 + 2 * tig] = make_float2(x0, y0);
        *(float2*)&g_attn[base + (size_t)(qg + 8) * DIM + n * 8 + 2 * tig] = make_float2(x8, y8);
    }
    #pragma unroll
    for (int off = 16; off; off >>= 1) amax = fmaxf(amax, __shfl_xor_sync(0xffffffffu, amax, off));
    float* sred = (float*)(smc + OB_SRED);
    if (lane == 0) sred[wid] = amax;
    __syncthreads();
    if (tid == 0) {
        float m = sred[0];
        #pragma unroll
        for (int i = 1; i < 8; i++) m = fmaxf(m, sred[i]);
        atomicMax(&g_absmax[5], __float_as_uint(m));
    }
}

// ---------------- launch ----------------
extern "C" void kernel_launch(void* const* d_in, const int* in_sizes, int n_in,
                              void* d_out, int out_size) {
    const float* hidden = (const float*)d_in[0];
    const float* mask   = (const float*)d_in[1];
    const float* Wq = (const float*)d_in[2];
    const float* bq = (const float*)d_in[3];
    const float* Wk = (const float*)d_in[4];
    const float* bk = (const float*)d_in[5];
    const float* Wv = (const float*)d_in[6];
    const float* bv = (const float*)d_in[7];
    const float* Wo = (const float*)d_in[8];
    const float* bo = (const float*)d_in[9];
    float* out = (float*)d_out;

    cudaFuncSetAttribute(attn_k, cudaFuncAttributeMaxDynamicSharedMemorySize, SMEM_ATTN);
    const int GEMM_SMEM = 3 * STG_BYTES;

    absmax_all_k<<<dim3(256, 5), 256>>>(hidden, Wq, Wk, Wv, Wo);            // 1
    quant_all_k<<<dim3(256, 5), 256>>>(hidden, Wq, Wk, Wv, Wo);             // 2
    gemm_qkv_k<<<dim3(DIM / BN2, (BB * SS) / BM2, 3), 256, GEMM_SMEM>>>(bq, bk, bv); // 3
    attn_k<<<dim3(SS / 128, HH, BB), 256, SMEM_ATTN>>>(mask);               // 4 <- ncu capture slot
    quant_attn_k<<<1024, 256>>>();                                          // 5
    gemm_o_k<<<dim3(DIM / BN2, (BB * SS) / BM2), 256, GEMM_SMEM>>>(bo, out); // 6
}